// round 6
// baseline (speedup 1.0000x reference)
#include <cuda_runtime.h>
#include <cuda_bf16.h>
#include <mma.h>
#include <math.h>

#define B_    8
#define C_    256
#define NPIX  4096
#define SROW  40
#define EPAD  132

using namespace nvcuda;

__device__ float          g_qk[(size_t)B_ * 64 * NPIX];
__device__ __nv_bfloat16  g_vb[(size_t)B_ * C_ * NPIX];
__device__ __nv_bfloat16  g_attb[(size_t)B_ * NPIX * NPIX];

// ---------------------------------------------------------------------------
// K1: fused QKV projection. q/k rows to g_qk (fp32), v rows to g_vb (bf16)
// ---------------------------------------------------------------------------
__global__ void proj_kernel(const float* __restrict__ x,
                            const float* __restrict__ Wq, const float* __restrict__ bq,
                            const float* __restrict__ Wk, const float* __restrict__ bk,
                            const float* __restrict__ Wv, const float* __restrict__ bv) {
    __shared__ float As[64 * 32];
    __shared__ __align__(16) float Xs[32 * 64];

    const int b  = blockIdx.z;
    const int o0 = blockIdx.y * 64;
    const int n0 = blockIdx.x * 64;
    const int tid = threadIdx.x;
    const int tx = tid & 15;
    const int ty = tid >> 4;

    const float* xb = x + (size_t)b * C_ * NPIX;
    float acc[4][4] = { };

    for (int k0 = 0; k0 < C_; k0 += 32) {
        const int wo = tid >> 2;
        const int wcid = (tid & 3) * 8;
        const int go = o0 + wo;
        const float* Wrow;
        if (go < 32) {
            Wrow = Wq + go * C_;
        } else if (go < 64) {
            Wrow = Wk + (go - 32) * C_;
        } else {
            Wrow = Wv + (go - 64) * C_;
        }
        #pragma unroll
        for (int u = 0; u < 8; ++u) As[wo * 32 + wcid + u] = Wrow[k0 + wcid + u];

        const int kk2 = tid >> 3;
        const int nj2 = (tid & 7) * 8;
        const float* xr = xb + (size_t)(k0 + kk2) * NPIX + n0 + nj2;
        #pragma unroll
        for (int u = 0; u < 8; ++u) Xs[kk2 * 64 + nj2 + u] = xr[u];

        __syncthreads();
        #pragma unroll
        for (int kk = 0; kk < 32; ++kk) {
            float4 xv = *(const float4*)&Xs[kk * 64 + tx * 4];
            #pragma unroll
            for (int ii = 0; ii < 4; ++ii) {
                float a = As[(ty * 4 + ii) * 32 + kk];
                acc[ii][0] += a * xv.x;
                acc[ii][1] += a * xv.y;
                acc[ii][2] += a * xv.z;
                acc[ii][3] += a * xv.w;
            }
        }
        __syncthreads();
    }

    #pragma unroll
    for (int ii = 0; ii < 4; ++ii) {
        const int o = o0 + ty * 4 + ii;
        float bias;
        if (o < 32) {
            bias = bq[o];
        } else if (o < 64) {
            bias = bk[o - 32];
        } else {
            bias = bv[o - 64];
        }
        if (o < 64) {
            float* dst = g_qk + ((size_t)b * 64 + o) * NPIX + n0 + tx * 4;
            #pragma unroll
            for (int jj = 0; jj < 4; ++jj) dst[jj] = acc[ii][jj] + bias;
        } else {
            __nv_bfloat16* dst = g_vb + ((size_t)b * C_ + (o - 64)) * NPIX + n0 + tx * 4;
            #pragma unroll
            for (int jj = 0; jj < 4; ++jj) dst[jj] = __float2bfloat16(acc[ii][jj] + bias);
        }
    }
}

// ---------------------------------------------------------------------------
// K2: energy via 3xTF32 tensor-core GEMM (fp32-accurate).
//   energy[n,m] = sum over c<32 of q[c,n]*k[c,m]
// CTA tile 128n x 128m, 8 warps each 32n x 64m. q split hi/lo in smem.
// A(n,c) = q[c][n] -> col_major; B(c,m) = k[c][m] -> row_major.
// ---------------------------------------------------------------------------
__global__ void __launch_bounds__(256)
energy_tf32_kernel(float* __restrict__ att) {
    __shared__ float qhi[32 * EPAD];
    __shared__ float qlo[32 * EPAD];
    __shared__ float khi[32 * EPAD];
    __shared__ float klo[32 * EPAD];

    const int b  = blockIdx.z;
    const int n0 = blockIdx.y * 128;
    const int m0 = blockIdx.x * 128;
    const int tid = threadIdx.x;

    const int lrow = tid >> 3;
    const int lcol = (tid & 7) * 16;
    const float* qg = g_qk + ((size_t)b * 64 + lrow) * NPIX + n0 + lcol;
    const float* kg = g_qk + ((size_t)b * 64 + 32 + lrow) * NPIX + m0 + lcol;
    #pragma unroll
    for (int u = 0; u < 16; ++u) {
        float qv = qg[u];
        float qh = wmma::__float_to_tf32(qv);
        qhi[lrow * EPAD + lcol + u] = qh;
        qlo[lrow * EPAD + lcol + u] = wmma::__float_to_tf32(qv - qh);
        float kv = kg[u];
        float kh = wmma::__float_to_tf32(kv);
        khi[lrow * EPAD + lcol + u] = kh;
        klo[lrow * EPAD + lcol + u] = wmma::__float_to_tf32(kv - kh);
    }
    __syncthreads();

    const int warp = tid >> 5;
    const int wn = (warp & 3) * 32;
    const int wm = (warp >> 2) * 64;

    wmma::fragment<wmma::accumulator, 16, 16, 8, float> acc[2][4];
    #pragma unroll
    for (int i = 0; i < 2; ++i) {
        #pragma unroll
        for (int j = 0; j < 4; ++j) wmma::fill_fragment(acc[i][j], 0.0f);
    }

    #pragma unroll
    for (int kc = 0; kc < 4; ++kc) {
        wmma::fragment<wmma::matrix_a, 16, 16, 8, wmma::precision::tf32, wmma::col_major> ahi[2], alo[2];
        wmma::fragment<wmma::matrix_b, 16, 16, 8, wmma::precision::tf32, wmma::row_major> bhi[4], blo[4];
        #pragma unroll
        for (int i = 0; i < 2; ++i) {
            wmma::load_matrix_sync(ahi[i], &qhi[(kc * 8) * EPAD + wn + 16 * i], EPAD);
            wmma::load_matrix_sync(alo[i], &qlo[(kc * 8) * EPAD + wn + 16 * i], EPAD);
        }
        #pragma unroll
        for (int j = 0; j < 4; ++j) {
            wmma::load_matrix_sync(bhi[j], &khi[(kc * 8) * EPAD + wm + 16 * j], EPAD);
            wmma::load_matrix_sync(blo[j], &klo[(kc * 8) * EPAD + wm + 16 * j], EPAD);
        }
        #pragma unroll
        for (int i = 0; i < 2; ++i) {
            #pragma unroll
            for (int j = 0; j < 4; ++j) {
                wmma::mma_sync(acc[i][j], ahi[i], blo[j], acc[i][j]);
                wmma::mma_sync(acc[i][j], alo[i], bhi[j], acc[i][j]);
                wmma::mma_sync(acc[i][j], ahi[i], bhi[j], acc[i][j]);
            }
        }
    }

    float* ob = att + (size_t)b * NPIX * NPIX;
    #pragma unroll
    for (int i = 0; i < 2; ++i) {
        #pragma unroll
        for (int j = 0; j < 4; ++j) {
            float* dst = ob + (size_t)(n0 + wn + 16 * i) * NPIX + m0 + wm + 16 * j;
            wmma::store_matrix_sync(dst, acc[i][j], NPIX, wmma::mem_row_major);
        }
    }
}

// ---------------------------------------------------------------------------
// K3: in-place row softmax plus bf16 copy. Each thread owns 16 contiguous
// elements -> float4 loads/stores, uint4 bf16 stores.
// ---------------------------------------------------------------------------
__global__ void softmax_kernel(float* __restrict__ att) {
    const int n = blockIdx.x;
    const int b = blockIdx.y;
    float* row = att + ((size_t)b * NPIX + n) * NPIX;
    __nv_bfloat16* rowb = g_attb + ((size_t)b * NPIX + n) * NPIX;
    const int t = threadIdx.x;
    const int base = t * 16;

    float v[16];
    float4* vp = (float4*)v;
    #pragma unroll
    for (int i = 0; i < 4; ++i) vp[i] = *(const float4*)&row[base + i * 4];

    float mx = v[0];
    #pragma unroll
    for (int i = 1; i < 16; ++i) mx = fmaxf(mx, v[i]);

    __shared__ float redm[8];
    #pragma unroll
    for (int o = 16; o; o >>= 1) mx = fmaxf(mx, __shfl_xor_sync(0xFFFFFFFFu, mx, o));
    if ((t & 31) == 0) redm[t >> 5] = mx;
    __syncthreads();
    mx = redm[0];
    #pragma unroll
    for (int w = 1; w < 8; ++w) mx = fmaxf(mx, redm[w]);

    float s = 0.f;
    #pragma unroll
    for (int i = 0; i < 16; ++i) {
        v[i] = expf(v[i] - mx);
        s += v[i];
    }
    __shared__ float reds[8];
    #pragma unroll
    for (int o = 16; o; o >>= 1) s += __shfl_xor_sync(0xFFFFFFFFu, s, o);
    if ((t & 31) == 0) reds[t >> 5] = s;
    __syncthreads();
    s = 0.f;
    #pragma unroll
    for (int w = 0; w < 8; ++w) s += reds[w];
    const float inv = 1.0f / s;

    #pragma unroll
    for (int i = 0; i < 16; ++i) v[i] *= inv;
    #pragma unroll
    for (int i = 0; i < 4; ++i) *(float4*)&row[base + i * 4] = vp[i];

    __align__(16) __nv_bfloat16 hb[16];
    #pragma unroll
    for (int i = 0; i < 16; ++i) hb[i] = __float2bfloat16(v[i]);
    const uint4* hp = (const uint4*)hb;
    *(uint4*)&rowb[base]     = hp[0];
    *(uint4*)&rowb[base + 8] = hp[1];
}

// ---------------------------------------------------------------------------
// K4: tensor-core AV GEMM via WMMA.
//   out[c,n] = 0.5*gamma*sum_m v[c,m]*att[n,m] + x[c,n]
// SROW=40 (80-byte rows) -> conflict-free ldmatrix bank pattern.
// ---------------------------------------------------------------------------
__global__ void __launch_bounds__(256, 2)
av_wmma_kernel(const float* __restrict__ x, const float* __restrict__ gamma,
               float* __restrict__ out) {
    __shared__ __align__(256) __nv_bfloat16 As[2][128 * SROW];
    __shared__ __align__(256) __nv_bfloat16 Bs[2][128 * SROW];

    const int b    = blockIdx.z;
    const int c0   = blockIdx.y * 128;
    const int n0   = blockIdx.x * 128;
    const int tid  = threadIdx.x;
    const int warp = tid >> 5;
    const int lane = tid & 31;
    const int wc   = (warp & 3) * 32;
    const int wn   = (warp >> 2) * 64;

    const __nv_bfloat16* vb = g_vb   + (size_t)b * C_ * NPIX;
    const __nv_bfloat16* ab = g_attb + (size_t)b * NPIX * NPIX;

    const int lrow  = tid >> 1;
    const int lhalf = (tid & 1) * 16;
    const __nv_bfloat16* gA = vb + (size_t)(c0 + lrow) * NPIX + lhalf;
    const __nv_bfloat16* gB = ab + (size_t)(n0 + lrow) * NPIX + lhalf;
    const int sOff = lrow * SROW + lhalf;

    wmma::fragment<wmma::accumulator, 16, 16, 16, float> acc[2][4];
    #pragma unroll
    for (int i = 0; i < 2; ++i) {
        #pragma unroll
        for (int j = 0; j < 4; ++j) wmma::fill_fragment(acc[i][j], 0.0f);
    }

    uint4 pa0 = *(const uint4*)(gA);
    uint4 pa1 = *(const uint4*)(gA + 8);
    uint4 pb0 = *(const uint4*)(gB);
    uint4 pb1 = *(const uint4*)(gB + 8);
    *(uint4*)&As[0][sOff]     = pa0;
    *(uint4*)&As[0][sOff + 8] = pa1;
    *(uint4*)&Bs[0][sOff]     = pb0;
    *(uint4*)&Bs[0][sOff + 8] = pb1;
    __syncthreads();

    for (int it = 0; it < 128; ++it) {
        const int cur = it & 1;
        uint4 na0, na1, nb0, nb1;
        if (it < 127) {
            const __nv_bfloat16* pA = gA + (it + 1) * 32;
            const __nv_bfloat16* pB = gB + (it + 1) * 32;
            na0 = *(const uint4*)(pA);
            na1 = *(const uint4*)(pA + 8);
            nb0 = *(const uint4*)(pB);
            nb1 = *(const uint4*)(pB + 8);
        }

        const __nv_bfloat16* Ab = &As[cur][0];
        const __nv_bfloat16* Bb = &Bs[cur][0];

        #pragma unroll
        for (int kk = 0; kk < 32; kk += 16) {
            wmma::fragment<wmma::matrix_a, 16, 16, 16, __nv_bfloat16, wmma::row_major> afrag[2];
            wmma::fragment<wmma::matrix_b, 16, 16, 16, __nv_bfloat16, wmma::col_major> bfrag[4];
            #pragma unroll
            for (int i = 0; i < 2; ++i) {
                wmma::load_matrix_sync(afrag[i], Ab + (wc + 16 * i) * SROW + kk, SROW);
            }
            #pragma unroll
            for (int j = 0; j < 4; ++j) {
                wmma::load_matrix_sync(bfrag[j], Bb + (wn + 16 * j) * SROW + kk, SROW);
            }
            #pragma unroll
            for (int i = 0; i < 2; ++i) {
                #pragma unroll
                for (int j = 0; j < 4; ++j) {
                    wmma::mma_sync(acc[i][j], afrag[i], bfrag[j], acc[i][j]);
                }
            }
        }

        if (it < 127) {
            const int nxt = cur ^ 1;
            *(uint4*)&As[nxt][sOff]     = na0;
            *(uint4*)&As[nxt][sOff + 8] = na1;
            *(uint4*)&Bs[nxt][sOff]     = nb0;
            *(uint4*)&Bs[nxt][sOff + 8] = nb1;
        }
        __syncthreads();
    }

    const float g = 0.5f * gamma[0];
    const float* xb = x   + (size_t)b * C_ * NPIX;
    float*       ob = out + (size_t)b * C_ * NPIX;
    float* stage = (float*)(&As[0][0]) + warp * 256;

    const int srow = lane >> 1;
    const int scol = (lane & 1) * 8;

    #pragma unroll
    for (int i = 0; i < 2; ++i) {
        #pragma unroll
        for (int j = 0; j < 4; ++j) {
            wmma::store_matrix_sync(stage, acc[i][j], 16, wmma::mem_row_major);
            __syncwarp();
            const int cc = c0 + wc + 16 * i + srow;
            const int nn = n0 + wn + 16 * j + scol;
            const size_t off = (size_t)cc * NPIX + nn;
            float4 s0 = *(const float4*)&stage[srow * 16 + scol];
            float4 s1 = *(const float4*)&stage[srow * 16 + scol + 4];
            float4 xv0 = *(const float4*)&xb[off];
            float4 xv1 = *(const float4*)&xb[off + 4];
            float4 ov0;
            float4 ov1;
            ov0.x = g * s0.x + xv0.x;
            ov0.y = g * s0.y + xv0.y;
            ov0.z = g * s0.z + xv0.z;
            ov0.w = g * s0.w + xv0.w;
            ov1.x = g * s1.x + xv1.x;
            ov1.y = g * s1.y + xv1.y;
            ov1.z = g * s1.z + xv1.z;
            ov1.w = g * s1.w + xv1.w;
            *(float4*)&ob[off]     = ov0;
            *(float4*)&ob[off + 4] = ov1;
            __syncwarp();
        }
    }
}

// ---------------------------------------------------------------------------
extern "C" void kernel_launch(void* const* d_in, const int* in_sizes, int n_in,
                              void* d_out, int out_size) {
    const float* x     = (const float*)d_in[0];
    const float* Wq    = (const float*)d_in[1];
    const float* bq    = (const float*)d_in[2];
    const float* Wk    = (const float*)d_in[3];
    const float* bk    = (const float*)d_in[4];
    const float* Wv    = (const float*)d_in[5];
    const float* bv    = (const float*)d_in[6];
    const float* gamma = (const float*)d_in[7];

    float* out = (float*)d_out;
    float* att = out + (size_t)B_ * C_ * NPIX;

    proj_kernel<<<dim3(64, 5, B_), 256>>>(x, Wq, bq, Wk, bk, Wv, bv);
    energy_tf32_kernel<<<dim3(32, 32, B_), 256>>>(att);
    softmax_kernel<<<dim3(NPIX, B_), 256>>>(att);
    av_wmma_kernel<<<dim3(32, 2, B_), 256>>>(x, gamma, out);
}

// round 8
// speedup vs baseline: 1.1991x; 1.1991x over previous
#include <cuda_runtime.h>
#include <cuda_bf16.h>
#include <mma.h>
#include <math.h>

#define B_    8
#define C_    256
#define NPIX  4096
#define SROW  40

using namespace nvcuda;

// q/k hi rows [0,64), lo rows [64,128)
__device__ __nv_bfloat16  g_qkb[(size_t)B_ * 128 * NPIX];
__device__ __nv_bfloat16  g_vb[(size_t)B_ * C_ * NPIX];
__device__ __nv_bfloat16  g_attb[(size_t)B_ * NPIX * NPIX];

// ---------------------------------------------------------------------------
// K1: fused QKV projection. q/k rows -> g_qkb as bf16 hi/lo split,
// v rows -> g_vb (bf16).
// ---------------------------------------------------------------------------
__global__ void proj_kernel(const float* __restrict__ x,
                            const float* __restrict__ Wq, const float* __restrict__ bq,
                            const float* __restrict__ Wk, const float* __restrict__ bk,
                            const float* __restrict__ Wv, const float* __restrict__ bv) {
    __shared__ float As[64 * 32];
    __shared__ __align__(16) float Xs[32 * 64];

    const int b  = blockIdx.z;
    const int o0 = blockIdx.y * 64;
    const int n0 = blockIdx.x * 64;
    const int tid = threadIdx.x;
    const int tx = tid & 15;
    const int ty = tid >> 4;

    const float* xb = x + (size_t)b * C_ * NPIX;
    float acc[4][4] = { };

    for (int k0 = 0; k0 < C_; k0 += 32) {
        const int wo = tid >> 2;
        const int wcid = (tid & 3) * 8;
        const int go = o0 + wo;
        const float* Wrow;
        if (go < 32) {
            Wrow = Wq + go * C_;
        } else if (go < 64) {
            Wrow = Wk + (go - 32) * C_;
        } else {
            Wrow = Wv + (go - 64) * C_;
        }
        #pragma unroll
        for (int u = 0; u < 8; ++u) As[wo * 32 + wcid + u] = Wrow[k0 + wcid + u];

        const int kk2 = tid >> 3;
        const int nj2 = (tid & 7) * 8;
        const float* xr = xb + (size_t)(k0 + kk2) * NPIX + n0 + nj2;
        #pragma unroll
        for (int u = 0; u < 8; ++u) Xs[kk2 * 64 + nj2 + u] = xr[u];

        __syncthreads();
        #pragma unroll
        for (int kk = 0; kk < 32; ++kk) {
            float4 xv = *(const float4*)&Xs[kk * 64 + tx * 4];
            #pragma unroll
            for (int ii = 0; ii < 4; ++ii) {
                float a = As[(ty * 4 + ii) * 32 + kk];
                acc[ii][0] += a * xv.x;
                acc[ii][1] += a * xv.y;
                acc[ii][2] += a * xv.z;
                acc[ii][3] += a * xv.w;
            }
        }
        __syncthreads();
    }

    #pragma unroll
    for (int ii = 0; ii < 4; ++ii) {
        const int o = o0 + ty * 4 + ii;
        float bias;
        if (o < 32) {
            bias = bq[o];
        } else if (o < 64) {
            bias = bk[o - 32];
        } else {
            bias = bv[o - 64];
        }
        if (o < 64) {
            __nv_bfloat16* dhi = g_qkb + ((size_t)b * 128 + o) * NPIX + n0 + tx * 4;
            __nv_bfloat16* dlo = dhi + (size_t)64 * NPIX;
            #pragma unroll
            for (int jj = 0; jj < 4; ++jj) {
                float val = acc[ii][jj] + bias;
                __nv_bfloat16 h = __float2bfloat16(val);
                dhi[jj] = h;
                dlo[jj] = __float2bfloat16(val - __bfloat162float(h));
            }
        } else {
            __nv_bfloat16* dst = g_vb + ((size_t)b * C_ + (o - 64)) * NPIX + n0 + tx * 4;
            #pragma unroll
            for (int jj = 0; jj < 4; ++jj) dst[jj] = __float2bfloat16(acc[ii][jj] + bias);
        }
    }
}

// ---------------------------------------------------------------------------
// K2: energy via split-bf16 WMMA straight from global memory.
//   energy = qh.kh + qh.kl + ql.kh  (missing ql.kl term ~2^-18 relative)
// A(n,c) = q[c][n]: col_major ld=NPIX.  B(c,m) = k[c][m]: row_major ld=NPIX.
// CTA 128n x 128m, 8 warps each 32n x 64m. Write-bound on 537MB output.
// ---------------------------------------------------------------------------
__global__ void __launch_bounds__(256)
energy_split_kernel(float* __restrict__ att) {
    const int b  = blockIdx.z;
    const int n0 = blockIdx.y * 128;
    const int m0 = blockIdx.x * 128;
    const int warp = threadIdx.x >> 5;
    const int wn = (warp & 3) * 32;
    const int wm = (warp >> 2) * 64;

    const __nv_bfloat16* qh = g_qkb + (size_t)b * 128 * NPIX;
    const __nv_bfloat16* kh = qh + (size_t)32 * NPIX;
    const __nv_bfloat16* ql = qh + (size_t)64 * NPIX;
    const __nv_bfloat16* kl = qh + (size_t)96 * NPIX;

    wmma::fragment<wmma::accumulator, 16, 16, 16, float> acc[2][4];
    #pragma unroll
    for (int i = 0; i < 2; ++i) {
        #pragma unroll
        for (int j = 0; j < 4; ++j) wmma::fill_fragment(acc[i][j], 0.0f);
    }

    #pragma unroll
    for (int ks = 0; ks < 2; ++ks) {
        wmma::fragment<wmma::matrix_a, 16, 16, 16, __nv_bfloat16, wmma::col_major> ah[2], al[2];
        wmma::fragment<wmma::matrix_b, 16, 16, 16, __nv_bfloat16, wmma::row_major> bh[4], bl[4];
        #pragma unroll
        for (int i = 0; i < 2; ++i) {
            wmma::load_matrix_sync(ah[i], qh + (size_t)(ks * 16) * NPIX + n0 + wn + 16 * i, NPIX);
            wmma::load_matrix_sync(al[i], ql + (size_t)(ks * 16) * NPIX + n0 + wn + 16 * i, NPIX);
        }
        #pragma unroll
        for (int j = 0; j < 4; ++j) {
            wmma::load_matrix_sync(bh[j], kh + (size_t)(ks * 16) * NPIX + m0 + wm + 16 * j, NPIX);
            wmma::load_matrix_sync(bl[j], kl + (size_t)(ks * 16) * NPIX + m0 + wm + 16 * j, NPIX);
        }
        #pragma unroll
        for (int i = 0; i < 2; ++i) {
            #pragma unroll
            for (int j = 0; j < 4; ++j) {
                wmma::mma_sync(acc[i][j], ah[i], bl[j], acc[i][j]);
                wmma::mma_sync(acc[i][j], al[i], bh[j], acc[i][j]);
                wmma::mma_sync(acc[i][j], ah[i], bh[j], acc[i][j]);
            }
        }
    }

    float* ob = att + (size_t)b * NPIX * NPIX;
    #pragma unroll
    for (int i = 0; i < 2; ++i) {
        #pragma unroll
        for (int j = 0; j < 4; ++j) {
            float* dst = ob + (size_t)(n0 + wn + 16 * i) * NPIX + m0 + wm + 16 * j;
            wmma::store_matrix_sync(dst, acc[i][j], NPIX, wmma::mem_row_major);
        }
    }
}

// ---------------------------------------------------------------------------
// K3: in-place row softmax plus bf16 copy. 16 contiguous elements per thread.
// ---------------------------------------------------------------------------
__global__ void softmax_kernel(float* __restrict__ att) {
    const int n = blockIdx.x;
    const int b = blockIdx.y;
    float* row = att + ((size_t)b * NPIX + n) * NPIX;
    __nv_bfloat16* rowb = g_attb + ((size_t)b * NPIX + n) * NPIX;
    const int t = threadIdx.x;
    const int base = t * 16;

    float v[16];
    float4* vp = (float4*)v;
    #pragma unroll
    for (int i = 0; i < 4; ++i) vp[i] = *(const float4*)&row[base + i * 4];

    float mx = v[0];
    #pragma unroll
    for (int i = 1; i < 16; ++i) mx = fmaxf(mx, v[i]);

    __shared__ float redm[8];
    #pragma unroll
    for (int o = 16; o; o >>= 1) mx = fmaxf(mx, __shfl_xor_sync(0xFFFFFFFFu, mx, o));
    if ((t & 31) == 0) redm[t >> 5] = mx;
    __syncthreads();
    mx = redm[0];
    #pragma unroll
    for (int w = 1; w < 8; ++w) mx = fmaxf(mx, redm[w]);

    float s = 0.f;
    #pragma unroll
    for (int i = 0; i < 16; ++i) {
        v[i] = expf(v[i] - mx);
        s += v[i];
    }
    __shared__ float reds[8];
    #pragma unroll
    for (int o = 16; o; o >>= 1) s += __shfl_xor_sync(0xFFFFFFFFu, s, o);
    if ((t & 31) == 0) reds[t >> 5] = s;
    __syncthreads();
    s = 0.f;
    #pragma unroll
    for (int w = 0; w < 8; ++w) s += reds[w];
    const float inv = 1.0f / s;

    #pragma unroll
    for (int i = 0; i < 16; ++i) v[i] *= inv;
    #pragma unroll
    for (int i = 0; i < 4; ++i) *(float4*)&row[base + i * 4] = vp[i];

    __align__(16) __nv_bfloat16 hb[16];
    #pragma unroll
    for (int i = 0; i < 16; ++i) hb[i] = __float2bfloat16(v[i]);
    const uint4* hp = (const uint4*)hb;
    *(uint4*)&rowb[base]     = hp[0];
    *(uint4*)&rowb[base + 8] = hp[1];
}

// ---------------------------------------------------------------------------
// K4: tensor-core AV GEMM via WMMA (unchanged: 386.7us in round 6).
//   out[c,n] = 0.5*gamma*sum_m v[c,m]*att[n,m] + x[c,n]
// ---------------------------------------------------------------------------
__global__ void __launch_bounds__(256, 2)
av_wmma_kernel(const float* __restrict__ x, const float* __restrict__ gamma,
               float* __restrict__ out) {
    __shared__ __align__(256) __nv_bfloat16 As[2][128 * SROW];
    __shared__ __align__(256) __nv_bfloat16 Bs[2][128 * SROW];

    const int b    = blockIdx.z;
    const int c0   = blockIdx.y * 128;
    const int n0   = blockIdx.x * 128;
    const int tid  = threadIdx.x;
    const int warp = tid >> 5;
    const int lane = tid & 31;
    const int wc   = (warp & 3) * 32;
    const int wn   = (warp >> 2) * 64;

    const __nv_bfloat16* vb = g_vb   + (size_t)b * C_ * NPIX;
    const __nv_bfloat16* ab = g_attb + (size_t)b * NPIX * NPIX;

    const int lrow  = tid >> 1;
    const int lhalf = (tid & 1) * 16;
    const __nv_bfloat16* gA = vb + (size_t)(c0 + lrow) * NPIX + lhalf;
    const __nv_bfloat16* gB = ab + (size_t)(n0 + lrow) * NPIX + lhalf;
    const int sOff = lrow * SROW + lhalf;

    wmma::fragment<wmma::accumulator, 16, 16, 16, float> acc[2][4];
    #pragma unroll
    for (int i = 0; i < 2; ++i) {
        #pragma unroll
        for (int j = 0; j < 4; ++j) wmma::fill_fragment(acc[i][j], 0.0f);
    }

    uint4 pa0 = *(const uint4*)(gA);
    uint4 pa1 = *(const uint4*)(gA + 8);
    uint4 pb0 = *(const uint4*)(gB);
    uint4 pb1 = *(const uint4*)(gB + 8);
    *(uint4*)&As[0][sOff]     = pa0;
    *(uint4*)&As[0][sOff + 8] = pa1;
    *(uint4*)&Bs[0][sOff]     = pb0;
    *(uint4*)&Bs[0][sOff + 8] = pb1;
    __syncthreads();

    for (int it = 0; it < 128; ++it) {
        const int cur = it & 1;
        uint4 na0, na1, nb0, nb1;
        if (it < 127) {
            const __nv_bfloat16* pA = gA + (it + 1) * 32;
            const __nv_bfloat16* pB = gB + (it + 1) * 32;
            na0 = *(const uint4*)(pA);
            na1 = *(const uint4*)(pA + 8);
            nb0 = *(const uint4*)(pB);
            nb1 = *(const uint4*)(pB + 8);
        }

        const __nv_bfloat16* Ab = &As[cur][0];
        const __nv_bfloat16* Bb = &Bs[cur][0];

        #pragma unroll
        for (int kk = 0; kk < 32; kk += 16) {
            wmma::fragment<wmma::matrix_a, 16, 16, 16, __nv_bfloat16, wmma::row_major> afrag[2];
            wmma::fragment<wmma::matrix_b, 16, 16, 16, __nv_bfloat16, wmma::col_major> bfrag[4];
            #pragma unroll
            for (int i = 0; i < 2; ++i) {
                wmma::load_matrix_sync(afrag[i], Ab + (wc + 16 * i) * SROW + kk, SROW);
            }
            #pragma unroll
            for (int j = 0; j < 4; ++j) {
                wmma::load_matrix_sync(bfrag[j], Bb + (wn + 16 * j) * SROW + kk, SROW);
            }
            #pragma unroll
            for (int i = 0; i < 2; ++i) {
                #pragma unroll
                for (int j = 0; j < 4; ++j) {
                    wmma::mma_sync(acc[i][j], afrag[i], bfrag[j], acc[i][j]);
                }
            }
        }

        if (it < 127) {
            const int nxt = cur ^ 1;
            *(uint4*)&As[nxt][sOff]     = na0;
            *(uint4*)&As[nxt][sOff + 8] = na1;
            *(uint4*)&Bs[nxt][sOff]     = nb0;
            *(uint4*)&Bs[nxt][sOff + 8] = nb1;
        }
        __syncthreads();
    }

    const float g = 0.5f * gamma[0];
    const float* xb = x   + (size_t)b * C_ * NPIX;
    float*       ob = out + (size_t)b * C_ * NPIX;
    float* stage = (float*)(&As[0][0]) + warp * 256;

    const int srow = lane >> 1;
    const int scol = (lane & 1) * 8;

    #pragma unroll
    for (int i = 0; i < 2; ++i) {
        #pragma unroll
        for (int j = 0; j < 4; ++j) {
            wmma::store_matrix_sync(stage, acc[i][j], 16, wmma::mem_row_major);
            __syncwarp();
            const int cc = c0 + wc + 16 * i + srow;
            const int nn = n0 + wn + 16 * j + scol;
            const size_t off = (size_t)cc * NPIX + nn;
            float4 s0 = *(const float4*)&stage[srow * 16 + scol];
            float4 s1 = *(const float4*)&stage[srow * 16 + scol + 4];
            float4 xv0 = *(const float4*)&xb[off];
            float4 xv1 = *(const float4*)&xb[off + 4];
            float4 ov0;
            float4 ov1;
            ov0.x = g * s0.x + xv0.x;
            ov0.y = g * s0.y + xv0.y;
            ov0.z = g * s0.z + xv0.z;
            ov0.w = g * s0.w + xv0.w;
            ov1.x = g * s1.x + xv1.x;
            ov1.y = g * s1.y + xv1.y;
            ov1.z = g * s1.z + xv1.z;
            ov1.w = g * s1.w + xv1.w;
            *(float4*)&ob[off]     = ov0;
            *(float4*)&ob[off + 4] = ov1;
            __syncwarp();
        }
    }
}

// ---------------------------------------------------------------------------
extern "C" void kernel_launch(void* const* d_in, const int* in_sizes, int n_in,
                              void* d_out, int out_size) {
    const float* x     = (const float*)d_in[0];
    const float* Wq    = (const float*)d_in[1];
    const float* bq    = (const float*)d_in[2];
    const float* Wk    = (const float*)d_in[3];
    const float* bk    = (const float*)d_in[4];
    const float* Wv    = (const float*)d_in[5];
    const float* bv    = (const float*)d_in[6];
    const float* gamma = (const float*)d_in[7];

    float* out = (float*)d_out;
    float* att = out + (size_t)B_ * C_ * NPIX;

    proj_kernel<<<dim3(64, 5, B_), 256>>>(x, Wq, bq, Wk, bk, Wv, bv);
    energy_split_kernel<<<dim3(32, 32, B_), 256>>>(att);
    softmax_kernel<<<dim3(NPIX, B_), 256>>>(att);
    av_wmma_kernel<<<dim3(32, 2, B_), 256>>>(x, gamma, out);
}